// round 1
// baseline (speedup 1.0000x reference)
#include <cuda_runtime.h>
#include <math.h>

#define D_MODEL   2048
#define D_INNER   4096
#define HN        64
#define D_HEAD    64
#define NSTATE    128
#define GRP       8
#define CHUNKL    256
#define GN_       1024
#define CONV_DIMC 6144
#define IN_PROJW  10304
#define BB        2
#define LSEQ      2048
#define NTOK      4096      // BB*LSEQ
#define NCHUNK    8         // LSEQ/CHUNKL
#define OUT_ELEMS 8388608   // BB*LSEQ*D_MODEL

// ---------------- scratch (static device globals; allocation-free) -------------
__device__ float g_xn   [(size_t)NTOK * D_MODEL];                 //  33.5 MB
__device__ float g_proj [(size_t)NTOK * IN_PROJW];                // 168.9 MB
__device__ float g_conv [(size_t)NTOK * CONV_DIMC];               // 100.7 MB
__device__ float g_Aval [(size_t)NTOK * HN];                      //   1 MB
__device__ float g_Acs  [(size_t)BB * NCHUNK * HN * CHUNKL];      //   1 MB
__device__ float g_states[(size_t)BB * NCHUNK * HN * NSTATE * D_HEAD]; // 33.5 MB
__device__ float g_hprev [(size_t)BB * NCHUNK * HN * NSTATE * D_HEAD]; // 33.5 MB
__device__ float g_Y    [(size_t)NTOK * D_INNER];                 //  67 MB

__device__ __forceinline__ float sigmoidf_(float v) { return 1.f / (1.f + expf(-v)); }
__device__ __forceinline__ float softplusf_(float v) { return v > 20.f ? v : log1pf(expf(v)); }

// ---------------- 1. rmsnorm(x) -> xn ------------------------------------------
__global__ void k_rms_x(const float* __restrict__ x, const float* __restrict__ w,
                        float* __restrict__ out) {
    int tok = blockIdx.x;
    const float* row = x + (size_t)tok * D_MODEL;
    __shared__ float red[256];
    float ss = 0.f;
    for (int i = threadIdx.x; i < D_MODEL; i += 256) { float v = row[i]; ss += v * v; }
    red[threadIdx.x] = ss; __syncthreads();
    for (int o = 128; o > 0; o >>= 1) { if (threadIdx.x < o) red[threadIdx.x] += red[threadIdx.x + o]; __syncthreads(); }
    float rms = rsqrtf(red[0] / D_MODEL + 1e-6f);
    float* orow = out + (size_t)tok * D_MODEL;
    for (int i = threadIdx.x; i < D_MODEL; i += 256) orow[i] = row[i] * rms * w[i];
}

// ---------------- generic fp32 GEMM: C[M,N] = A[M,K] @ B[N,K]^T (+resid) -------
// grid: (N/64, M/128), block 256. per-thread 8x4.
__global__ void k_gemm(const float* __restrict__ A, const float* __restrict__ B,
                       float* __restrict__ C, const float* __restrict__ R,
                       int M, int N, int K) {
    __shared__ float As[128][17];
    __shared__ float Bs[64][17];
    int n0 = blockIdx.x * 64, m0 = blockIdx.y * 128;
    int tid = threadIdx.x;
    int tn = tid & 15, tm = tid >> 4;
    float acc[8][4];
    #pragma unroll
    for (int i = 0; i < 8; i++)
        #pragma unroll
        for (int j = 0; j < 4; j++) acc[i][j] = 0.f;

    for (int k0 = 0; k0 < K; k0 += 16) {
        for (int idx = tid; idx < 128 * 16; idx += 256) {
            int r = idx >> 4, cc = idx & 15;
            As[r][cc] = A[(size_t)(m0 + r) * K + k0 + cc];
        }
        for (int idx = tid; idx < 64 * 16; idx += 256) {
            int r = idx >> 4, cc = idx & 15;
            Bs[r][cc] = B[(size_t)(n0 + r) * K + k0 + cc];
        }
        __syncthreads();
        #pragma unroll
        for (int kk = 0; kk < 16; kk++) {
            float a[8], bb[4];
            #pragma unroll
            for (int i = 0; i < 8; i++) a[i] = As[tm * 8 + i][kk];
            #pragma unroll
            for (int j = 0; j < 4; j++) bb[j] = Bs[tn * 4 + j][kk];
            #pragma unroll
            for (int i = 0; i < 8; i++)
                #pragma unroll
                for (int j = 0; j < 4; j++) acc[i][j] += a[i] * bb[j];
        }
        __syncthreads();
    }
    #pragma unroll
    for (int i = 0; i < 8; i++)
        #pragma unroll
        for (int j = 0; j < 4; j++) {
            size_t off = (size_t)(m0 + tm * 8 + i) * N + (n0 + tn * 4 + j);
            float v = acc[i][j];
            if (R) v += R[off];
            C[off] = v;
        }
}

// ---------------- 3. conv4 + bias + rmsnorm + silu -> g_conv -------------------
// one block per token; each thread handles 24 channels (strided).
__global__ void k_conv(const float* __restrict__ proj, const float* __restrict__ cw,
                       const float* __restrict__ cb, const float* __restrict__ nw,
                       float* __restrict__ out) {
    int tok = blockIdx.x;
    int l = tok & (LSEQ - 1);
    float v[24];
    float ss = 0.f;
    #pragma unroll
    for (int k = 0; k < 24; k++) {
        int c = threadIdx.x + k * 256;
        int pcol = (c < D_INNER) ? c : c + HN;   // skip A_dt slot in proj
        float acc = cb[c];
        #pragma unroll
        for (int j = 0; j < 4; j++) {
            int lj = l + j - 3;
            if (lj >= 0)
                acc += cw[c * 4 + j] * proj[(size_t)(tok + j - 3) * IN_PROJW + pcol];
        }
        v[k] = acc;
        ss += acc * acc;
    }
    __shared__ float red[256];
    red[threadIdx.x] = ss; __syncthreads();
    for (int o = 128; o > 0; o >>= 1) { if (threadIdx.x < o) red[threadIdx.x] += red[threadIdx.x + o]; __syncthreads(); }
    float rms = rsqrtf(red[0] / CONV_DIMC + 1e-6f);
    #pragma unroll
    for (int k = 0; k < 24; k++) {
        int c = threadIdx.x + k * 256;
        float y = v[k] * rms * nw[c];
        out[(size_t)tok * CONV_DIMC + c] = y * sigmoidf_(y);
    }
}

// ---------------- 4. dt -> A ---------------------------------------------------
__global__ void k_dt(const float* __restrict__ proj, const float* __restrict__ dtw,
                     const float* __restrict__ dtb, const float* __restrict__ alog,
                     float* __restrict__ Aout) {
    int tok = blockIdx.x;
    __shared__ float sa[HN];
    sa[threadIdx.x] = proj[(size_t)tok * IN_PROJW + D_INNER + threadIdx.x];
    __syncthreads();
    int h = threadIdx.x;
    float acc = dtb[h];
    #pragma unroll
    for (int k = 0; k < HN; k++) acc += sa[k] * dtw[h * HN + k];
    float dt = softplusf_(acc);
    Aout[(size_t)tok * HN + h] = -expf(alog[h]) * dt;
}

// ---------------- 5. cumsum of A per (b,c,h) -----------------------------------
__global__ void k_cumsum(const float* __restrict__ Aval, float* __restrict__ Acs) {
    int bid = blockIdx.x;                       // b*512 + c*64 + h
    int h = bid & 63, c = (bid >> 6) & 7, b = bid >> 9;
    int t = threadIdx.x;
    int tok = b * LSEQ + c * CHUNKL + t;
    __shared__ float s[CHUNKL];
    s[t] = Aval[(size_t)tok * HN + h];
    __syncthreads();
    for (int off = 1; off < CHUNKL; off <<= 1) {
        float add = (t >= off) ? s[t - off] : 0.f;
        __syncthreads();
        s[t] += add;
        __syncthreads();
    }
    Acs[(size_t)bid * CHUNKL + t] = s[t];
}

// ---------------- 6. per-chunk states[n,d] -------------------------------------
__global__ void k_states(const float* __restrict__ conv, const float* __restrict__ Acs,
                         float* __restrict__ states) {
    int bid = blockIdx.x;                       // b*512 + c*64 + h
    int h = bid & 63, c = (bid >> 6) & 7, b = bid >> 9;
    int g = h >> 3;
    int base_tok = b * LSEQ + c * CHUNKL;
    float A_last = Acs[(size_t)bid * CHUNKL + 255];

    __shared__ float sX[8][64];
    __shared__ float sB[8][128];
    __shared__ float sdec[8];

    int n = threadIdx.x & 127;
    int dq = threadIdx.x >> 7;                  // 0/1 -> d block of 32
    float acc[32];
    #pragma unroll
    for (int i = 0; i < 32; i++) acc[i] = 0.f;

    for (int t0 = 0; t0 < CHUNKL; t0 += 8) {
        for (int idx = threadIdx.x; idx < 8 * 64; idx += 256) {
            int r = idx >> 6, dd = idx & 63;
            sX[r][dd] = conv[(size_t)(base_tok + t0 + r) * CONV_DIMC + h * 64 + dd];
        }
        for (int idx = threadIdx.x; idx < 8 * 128; idx += 256) {
            int r = idx >> 7, nn = idx & 127;
            sB[r][nn] = conv[(size_t)(base_tok + t0 + r) * CONV_DIMC + D_INNER + g * 128 + nn];
        }
        if (threadIdx.x < 8)
            sdec[threadIdx.x] = expf(A_last - Acs[(size_t)bid * CHUNKL + t0 + threadIdx.x]);
        __syncthreads();
        #pragma unroll
        for (int r = 0; r < 8; r++) {
            float bv = sB[r][n] * sdec[r];
            #pragma unroll
            for (int i = 0; i < 32; i++) acc[i] += bv * sX[r][dq * 32 + i];
        }
        __syncthreads();
    }
    size_t base = (size_t)bid * (NSTATE * D_HEAD) + (size_t)n * D_HEAD + dq * 32;
    #pragma unroll
    for (int i = 0; i < 32; i++) states[base + i] = acc[i];
}

// ---------------- 7. inter-chunk scan ------------------------------------------
__global__ void k_scan(const float* __restrict__ states, const float* __restrict__ Acs,
                       float* __restrict__ hprev, float* __restrict__ hfinal) {
    int bh = blockIdx.x;                        // b*64 + h
    int b = bh >> 6, h = bh & 63;
    float hv[32];
    #pragma unroll
    for (int k = 0; k < 32; k++) hv[k] = 0.f;
    for (int c = 0; c < NCHUNK; c++) {
        int bid = b * 512 + c * 64 + h;
        float cd = expf(Acs[(size_t)bid * CHUNKL + 255]);
        size_t base = (size_t)bid * (NSTATE * D_HEAD);
        #pragma unroll
        for (int k = 0; k < 32; k++) {
            int e = threadIdx.x + k * 256;
            hprev[base + e] = hv[k];
            hv[k] = hv[k] * cd + states[base + e];
        }
    }
    size_t obase = (size_t)bh * (NSTATE * D_HEAD);
    #pragma unroll
    for (int k = 0; k < 32; k++) hfinal[obase + threadIdx.x + k * 256] = hv[k];
}

// ---------------- 8. Y = Y_diag + Y_carry --------------------------------------
// grid: b*2048 + c*256 + h*4 + tblk (4096 blocks), 256 threads, dyn smem ~106KB
__global__ void k_y(const float* __restrict__ conv, const float* __restrict__ Acs,
                    const float* __restrict__ hprev, float* __restrict__ Y) {
    int bid = blockIdx.x;
    int tblk = bid & 3, h = (bid >> 2) & 63, c = (bid >> 8) & 7, b = bid >> 11;
    int g = h >> 3;
    int bch = b * 512 + c * 64 + h;
    int base_tok = b * LSEQ + c * CHUNKL;
    int t0 = tblk * 64;

    extern __shared__ float sm[];
    float* sAcs = sm;                  // 256
    float* sC   = sAcs + 256;          // 64*129
    float* sB   = sC + 64 * 129;       // 64*129
    float* sX   = sB + 64 * 129;       // 64*65
    float* sP   = sX + 64 * 65;        // 64*65
    float* sH   = sP + 64 * 65;        // 32*65

    int tid = threadIdx.x;
    int i = tid >> 2;                  // t row within tile (0..63)
    int q = tid & 3;                   // quarter (16 cols of d / 16 cols of s)

    if (tid < 256) sAcs[tid] = Acs[(size_t)bch * CHUNKL + tid];
    for (int idx = tid; idx < 64 * 128; idx += 256) {
        int r = idx >> 7, n = idx & 127;
        sC[r * 129 + n] = conv[(size_t)(base_tok + t0 + r) * CONV_DIMC + D_INNER + GN_ + g * 128 + n];
    }
    __syncthreads();

    float acc[16];
    #pragma unroll
    for (int d = 0; d < 16; d++) acc[d] = 0.f;

    // ---- carry: C @ h_prev ----
    for (int nt = 0; nt < 4; nt++) {
        for (int idx = tid; idx < 32 * 64; idx += 256) {
            int r = idx >> 6, dd = idx & 63;
            sH[r * 65 + dd] = hprev[(size_t)bch * (NSTATE * D_HEAD) + (size_t)(nt * 32 + r) * D_HEAD + dd];
        }
        __syncthreads();
        #pragma unroll
        for (int nl = 0; nl < 32; nl++) {
            float cv = sC[i * 129 + nt * 32 + nl];
            #pragma unroll
            for (int d = 0; d < 16; d++) acc[d] += cv * sH[nl * 65 + q * 16 + d];
        }
        __syncthreads();
    }
    {
        float eA = expf(sAcs[t0 + i]);
        #pragma unroll
        for (int d = 0; d < 16; d++) acc[d] *= eA;
    }

    // ---- diag: (L .* CB) @ X over s-tiles ----
    for (int st = 0; st <= tblk; st++) {
        for (int idx = tid; idx < 64 * 128; idx += 256) {
            int r = idx >> 7, n = idx & 127;
            sB[r * 129 + n] = conv[(size_t)(base_tok + st * 64 + r) * CONV_DIMC + D_INNER + g * 128 + n];
        }
        for (int idx = tid; idx < 64 * 64; idx += 256) {
            int r = idx >> 6, dd = idx & 63;
            sX[r * 65 + dd] = conv[(size_t)(base_tok + st * 64 + r) * CONV_DIMC + h * 64 + dd];
        }
        __syncthreads();
        int tg = t0 + i;
        float at = sAcs[tg];
        #pragma unroll
        for (int jj = 0; jj < 16; jj++) {
            int j = q * 16 + jj;
            float p = 0.f;
            #pragma unroll
            for (int n = 0; n < 128; n++) p += sC[i * 129 + n] * sB[j * 129 + n];
            int sg = st * 64 + j;
            sP[i * 65 + j] = (sg <= tg) ? expf(at - sAcs[sg]) * p : 0.f;
        }
        __syncthreads();
        #pragma unroll
        for (int j = 0; j < 64; j++) {
            float pv = sP[i * 65 + j];
            #pragma unroll
            for (int d = 0; d < 16; d++) acc[d] += pv * sX[j * 65 + q * 16 + d];
        }
        __syncthreads();
    }

    int tok = base_tok + t0 + i;
    size_t obase = (size_t)tok * D_INNER + h * 64 + q * 16;
    #pragma unroll
    for (int d = 0; d < 16; d++) Y[obase + d] = acc[d];
}

// ---------------- 9. out-norm * silu(gate), in place on Y ----------------------
__global__ void k_ynorm(float* __restrict__ Y, const float* __restrict__ proj,
                        const float* __restrict__ w) {
    int tok = blockIdx.x;
    float* row = Y + (size_t)tok * D_INNER;
    __shared__ float red[256];
    float ss = 0.f;
    for (int i = threadIdx.x; i < D_INNER; i += 256) { float v = row[i]; ss += v * v; }
    red[threadIdx.x] = ss; __syncthreads();
    for (int o = 128; o > 0; o >>= 1) { if (threadIdx.x < o) red[threadIdx.x] += red[threadIdx.x + o]; __syncthreads(); }
    float rms = rsqrtf(red[0] / D_INNER + 1e-6f);
    const float* grow = proj + (size_t)tok * IN_PROJW + (D_INNER + HN + 2 * GN_);
    for (int i = threadIdx.x; i < D_INNER; i += 256) {
        float y = row[i] * rms * w[i];
        float gv = grow[i];
        row[i] = y * gv * sigmoidf_(gv);
    }
}

// ---------------- launch -------------------------------------------------------
extern "C" void kernel_launch(void* const* d_in, const int* in_sizes, int n_in,
                              void* d_out, int out_size) {
    const float* x       = (const float*)d_in[0];
    const float* norm_w  = (const float*)d_in[1];
    const float* inw     = (const float*)d_in[2];
    const float* cw      = (const float*)d_in[3];
    const float* cb      = (const float*)d_in[4];
    const float* cnw     = (const float*)d_in[5];
    const float* alog    = (const float*)d_in[6];
    const float* dtw     = (const float*)d_in[7];
    const float* dtb     = (const float*)d_in[8];
    const float* onw     = (const float*)d_in[9];
    const float* ow      = (const float*)d_in[10];
    float* out = (float*)d_out;

    float *xn, *proj, *conv, *Aval, *Acs, *states, *hprev, *Y;
    cudaGetSymbolAddress((void**)&xn,     g_xn);
    cudaGetSymbolAddress((void**)&proj,   g_proj);
    cudaGetSymbolAddress((void**)&conv,   g_conv);
    cudaGetSymbolAddress((void**)&Aval,   g_Aval);
    cudaGetSymbolAddress((void**)&Acs,    g_Acs);
    cudaGetSymbolAddress((void**)&states, g_states);
    cudaGetSymbolAddress((void**)&hprev,  g_hprev);
    cudaGetSymbolAddress((void**)&Y,      g_Y);

    cudaFuncSetAttribute(k_y, cudaFuncAttributeMaxDynamicSharedMemorySize, 120000);
    size_t y_smem = (256 + 64 * 129 * 2 + 64 * 65 * 2 + 32 * 65) * sizeof(float);

    k_rms_x<<<NTOK, 256>>>(x, norm_w, xn);
    k_gemm<<<dim3(IN_PROJW / 64, NTOK / 128), 256>>>(xn, inw, proj, nullptr, NTOK, IN_PROJW, D_MODEL);
    k_conv<<<NTOK, 256>>>(proj, cw, cb, cnw, conv);
    k_dt<<<NTOK, HN>>>(proj, dtw, dtb, alog, Aval);
    k_cumsum<<<BB * NCHUNK * HN, CHUNKL>>>(Aval, Acs);
    k_states<<<BB * NCHUNK * HN, 256>>>(conv, Acs, states);
    k_scan<<<BB * HN, 256>>>(states, Acs, hprev, out + OUT_ELEMS);
    k_y<<<BB * NCHUNK * HN * 4, 256, y_smem>>>(conv, Acs, hprev, Y);
    k_ynorm<<<NTOK, 256>>>(Y, proj, onw);
    k_gemm<<<dim3(D_MODEL / 64, NTOK / 128), 256>>>(Y, ow, out, x, NTOK, D_MODEL, D_INNER);
}

// round 9
// speedup vs baseline: 2.4176x; 2.4176x over previous
#include <cuda_runtime.h>
#include <math.h>
#include <stdint.h>

#define D_MODEL   2048
#define D_INNER   4096
#define HN        64
#define D_HEAD    64
#define NSTATE    128
#define GRP       8
#define CHUNKL    256
#define GN_       1024
#define CONV_DIMC 6144
#define IN_PROJW  10304
#define BB        2
#define LSEQ      2048
#define NTOK      4096      // BB*LSEQ
#define NCHUNK    8         // LSEQ/CHUNKL
#define OUT_ELEMS 8388608   // BB*LSEQ*D_MODEL

// ---------------- scratch (static device globals; allocation-free) -------------
__device__ float g_xn   [(size_t)NTOK * D_MODEL];
__device__ float g_proj [(size_t)NTOK * IN_PROJW];
__device__ float g_conv [(size_t)NTOK * CONV_DIMC];
__device__ float g_Aval [(size_t)NTOK * HN];
__device__ float g_Acs  [(size_t)BB * NCHUNK * HN * CHUNKL];
__device__ float g_states[(size_t)BB * NCHUNK * HN * NSTATE * D_HEAD];
__device__ float g_hprev [(size_t)BB * NCHUNK * HN * NSTATE * D_HEAD];
__device__ float g_Y    [(size_t)NTOK * D_INNER];

__device__ __forceinline__ float sigmoidf_(float v) { return 1.f / (1.f + expf(-v)); }
__device__ __forceinline__ float softplusf_(float v) { return v > 20.f ? v : log1pf(expf(v)); }
__device__ __forceinline__ float tf32r_(float x) {
    uint32_t u;
    asm("cvt.rna.tf32.f32 %0, %1;" : "=r"(u) : "f"(x));
    return __uint_as_float(u);
}
__device__ __forceinline__ void mma_tf32_(float* d, const uint32_t* a, const uint32_t* b) {
    asm volatile(
        "mma.sync.aligned.m16n8k8.row.col.f32.tf32.tf32.f32 "
        "{%0,%1,%2,%3}, {%4,%5,%6,%7}, {%8,%9}, {%0,%1,%2,%3};\n"
        : "+f"(d[0]), "+f"(d[1]), "+f"(d[2]), "+f"(d[3])
        : "r"(a[0]), "r"(a[1]), "r"(a[2]), "r"(a[3]), "r"(b[0]), "r"(b[1]));
}

// ---------------- 1. rmsnorm(x) -> xn ------------------------------------------
__global__ void k_rms_x(const float* __restrict__ x, const float* __restrict__ w,
                        float* __restrict__ out) {
    int tok = blockIdx.x;
    const float* row = x + (size_t)tok * D_MODEL;
    __shared__ float red[256];
    float ss = 0.f;
    for (int i = threadIdx.x; i < D_MODEL; i += 256) { float v = row[i]; ss += v * v; }
    red[threadIdx.x] = ss; __syncthreads();
    for (int o = 128; o > 0; o >>= 1) { if (threadIdx.x < o) red[threadIdx.x] += red[threadIdx.x + o]; __syncthreads(); }
    float rms = rsqrtf(red[0] / D_MODEL + 1e-6f);
    float* orow = out + (size_t)tok * D_MODEL;
    for (int i = threadIdx.x; i < D_MODEL; i += 256) orow[i] = row[i] * rms * w[i];
}

// ---------------- TF32 tensor-core GEMM: C[M,N] = A[M,K] @ B[N,K]^T (+resid) ---
// BM=128, BN=64, BK=32. 128 threads = 4 warps, 2x2 warp grid, each warp 64x32.
// smem rows padded to 36 floats -> fragment LDS bank-conflict-free (4g+tg map).
// Double-buffered; global prefetch staged in registers; cvt.rna at smem store.
#define GT_PAD 36
#define GT_ABUF (128 * GT_PAD)
#define GT_BBUF (64 * GT_PAD)
__global__ __launch_bounds__(128, 3)
void k_gemm_tf32(const float* __restrict__ A, const float* __restrict__ B,
                 float* __restrict__ C, const float* __restrict__ R,
                 int M, int N, int K) {
    extern __shared__ float sm[];
    float* sA = sm;                   // [2][128][36]
    float* sB = sm + 2 * GT_ABUF;     // [2][64][36]

    const int tid  = threadIdx.x;
    const int lane = tid & 31;
    const int w    = tid >> 5;
    const int wm   = w >> 1, wn = w & 1;
    const int g    = lane >> 2, tg = lane & 3;
    const int m0 = blockIdx.y * 128, n0 = blockIdx.x * 64;

    float4 pa[8], pb[4];
    #pragma unroll
    for (int p = 0; p < 8; p++) {
        int idx = tid + p * 128; int r = idx >> 3, c = idx & 7;
        pa[p] = *(const float4*)&A[(size_t)(m0 + r) * K + c * 4];
    }
    #pragma unroll
    for (int p = 0; p < 4; p++) {
        int idx = tid + p * 128; int r = idx >> 3, c = idx & 7;
        pb[p] = *(const float4*)&B[(size_t)(n0 + r) * K + c * 4];
    }

    float acc[4][4][4];
    #pragma unroll
    for (int mi = 0; mi < 4; mi++)
        #pragma unroll
        for (int ni = 0; ni < 4; ni++)
            #pragma unroll
            for (int e = 0; e < 4; e++) acc[mi][ni][e] = 0.f;

    const int nk = K >> 5;
    int buf = 0;

    // store prologue tile (with tf32 rounding)
    #pragma unroll
    for (int p = 0; p < 8; p++) {
        int idx = tid + p * 128; int r = idx >> 3, c = idx & 7;
        float4 v = pa[p];
        v.x = tf32r_(v.x); v.y = tf32r_(v.y); v.z = tf32r_(v.z); v.w = tf32r_(v.w);
        *(float4*)&sA[r * GT_PAD + c * 4] = v;
    }
    #pragma unroll
    for (int p = 0; p < 4; p++) {
        int idx = tid + p * 128; int r = idx >> 3, c = idx & 7;
        float4 v = pb[p];
        v.x = tf32r_(v.x); v.y = tf32r_(v.y); v.z = tf32r_(v.z); v.w = tf32r_(v.w);
        *(float4*)&sB[r * GT_PAD + c * 4] = v;
    }
    __syncthreads();

    for (int kt = 0; kt < nk; kt++) {
        // prefetch next tile into registers
        if (kt + 1 < nk) {
            int k0 = (kt + 1) * 32;
            #pragma unroll
            for (int p = 0; p < 8; p++) {
                int idx = tid + p * 128; int r = idx >> 3, c = idx & 7;
                pa[p] = *(const float4*)&A[(size_t)(m0 + r) * K + k0 + c * 4];
            }
            #pragma unroll
            for (int p = 0; p < 4; p++) {
                int idx = tid + p * 128; int r = idx >> 3, c = idx & 7;
                pb[p] = *(const float4*)&B[(size_t)(n0 + r) * K + k0 + c * 4];
            }
        }

        const float* cA = sA + buf * GT_ABUF + (wm * 64) * GT_PAD;
        const float* cB = sB + buf * GT_BBUF + (wn * 32) * GT_PAD;
        #pragma unroll
        for (int ks = 0; ks < 4; ks++) {
            const int kk = ks * 8;
            uint32_t af[4][4], bf[4][2];
            #pragma unroll
            for (int mi = 0; mi < 4; mi++) {
                af[mi][0] = __float_as_uint(cA[(mi * 16 + g) * GT_PAD + kk + tg]);
                af[mi][1] = __float_as_uint(cA[(mi * 16 + 8 + g) * GT_PAD + kk + tg]);
                af[mi][2] = __float_as_uint(cA[(mi * 16 + g) * GT_PAD + kk + tg + 4]);
                af[mi][3] = __float_as_uint(cA[(mi * 16 + 8 + g) * GT_PAD + kk + tg + 4]);
            }
            #pragma unroll
            for (int ni = 0; ni < 4; ni++) {
                bf[ni][0] = __float_as_uint(cB[(ni * 8 + g) * GT_PAD + kk + tg]);
                bf[ni][1] = __float_as_uint(cB[(ni * 8 + g) * GT_PAD + kk + tg + 4]);
            }
            #pragma unroll
            for (int mi = 0; mi < 4; mi++)
                #pragma unroll
                for (int ni = 0; ni < 4; ni++)
                    mma_tf32_(acc[mi][ni], af[mi], bf[ni]);
        }

        if (kt + 1 < nk) {
            int nb = buf ^ 1;
            #pragma unroll
            for (int p = 0; p < 8; p++) {
                int idx = tid + p * 128; int r = idx >> 3, c = idx & 7;
                float4 v = pa[p];
                v.x = tf32r_(v.x); v.y = tf32r_(v.y); v.z = tf32r_(v.z); v.w = tf32r_(v.w);
                *(float4*)&sA[nb * GT_ABUF + r * GT_PAD + c * 4] = v;
            }
            #pragma unroll
            for (int p = 0; p < 4; p++) {
                int idx = tid + p * 128; int r = idx >> 3, c = idx & 7;
                float4 v = pb[p];
                v.x = tf32r_(v.x); v.y = tf32r_(v.y); v.z = tf32r_(v.z); v.w = tf32r_(v.w);
                *(float4*)&sB[nb * GT_BBUF + r * GT_PAD + c * 4] = v;
            }
            __syncthreads();
            buf = nb;
        }
    }

    // epilogue
    #pragma unroll
    for (int mi = 0; mi < 4; mi++) {
        #pragma unroll
        for (int ni = 0; ni < 4; ni++) {
            int row = m0 + wm * 64 + mi * 16 + g;
            int col = n0 + wn * 32 + ni * 8 + tg * 2;
            size_t o0 = (size_t)row * N + col;
            size_t o1 = (size_t)(row + 8) * N + col;
            float2 v0 = make_float2(acc[mi][ni][0], acc[mi][ni][1]);
            float2 v1 = make_float2(acc[mi][ni][2], acc[mi][ni][3]);
            if (R) {
                float2 r0 = *(const float2*)&R[o0];
                float2 r1 = *(const float2*)&R[o1];
                v0.x += r0.x; v0.y += r0.y; v1.x += r1.x; v1.y += r1.y;
            }
            *(float2*)&C[o0] = v0;
            *(float2*)&C[o1] = v1;
        }
    }
}

// ---------------- 3. conv4 + bias + rmsnorm + silu -> g_conv -------------------
__global__ void k_conv(const float* __restrict__ proj, const float* __restrict__ cw,
                       const float* __restrict__ cb, const float* __restrict__ nw,
                       float* __restrict__ out) {
    int tok = blockIdx.x;
    int l = tok & (LSEQ - 1);
    float v[24];
    float ss = 0.f;
    #pragma unroll
    for (int k = 0; k < 24; k++) {
        int c = threadIdx.x + k * 256;
        int pcol = (c < D_INNER) ? c : c + HN;
        float acc = cb[c];
        #pragma unroll
        for (int j = 0; j < 4; j++) {
            int lj = l + j - 3;
            if (lj >= 0)
                acc += cw[c * 4 + j] * proj[(size_t)(tok + j - 3) * IN_PROJW + pcol];
        }
        v[k] = acc;
        ss += acc * acc;
    }
    __shared__ float red[256];
    red[threadIdx.x] = ss; __syncthreads();
    for (int o = 128; o > 0; o >>= 1) { if (threadIdx.x < o) red[threadIdx.x] += red[threadIdx.x + o]; __syncthreads(); }
    float rms = rsqrtf(red[0] / CONV_DIMC + 1e-6f);
    #pragma unroll
    for (int k = 0; k < 24; k++) {
        int c = threadIdx.x + k * 256;
        float y = v[k] * rms * nw[c];
        out[(size_t)tok * CONV_DIMC + c] = y * sigmoidf_(y);
    }
}

// ---------------- 4. dt -> A (4 tokens per block) ------------------------------
__global__ void k_dt(const float* __restrict__ proj, const float* __restrict__ dtw,
                     const float* __restrict__ dtb, const float* __restrict__ alog,
                     float* __restrict__ Aout) {
    int sub = threadIdx.x >> 6;
    int h = threadIdx.x & 63;
    int tok = blockIdx.x * 4 + sub;
    __shared__ float sa[4][HN];
    sa[sub][h] = proj[(size_t)tok * IN_PROJW + D_INNER + h];
    __syncthreads();
    float acc = dtb[h];
    #pragma unroll
    for (int k = 0; k < HN; k++) acc += sa[sub][k] * dtw[h * HN + k];
    float dt = softplusf_(acc);
    Aout[(size_t)tok * HN + h] = -expf(alog[h]) * dt;
}

// ---------------- 5. cumsum of A per (b,c,h) -----------------------------------
__global__ void k_cumsum(const float* __restrict__ Aval, float* __restrict__ Acs) {
    int bid = blockIdx.x;
    int h = bid & 63, c = (bid >> 6) & 7, b = bid >> 9;
    int t = threadIdx.x;
    int tok = b * LSEQ + c * CHUNKL + t;
    __shared__ float s[CHUNKL];
    s[t] = Aval[(size_t)tok * HN + h];
    __syncthreads();
    for (int off = 1; off < CHUNKL; off <<= 1) {
        float add = (t >= off) ? s[t - off] : 0.f;
        __syncthreads();
        s[t] += add;
        __syncthreads();
    }
    Acs[(size_t)bid * CHUNKL + t] = s[t];
}

// ---------------- 6. per-chunk states[n,d] -------------------------------------
__global__ void k_states(const float* __restrict__ conv, const float* __restrict__ Acs,
                         float* __restrict__ states) {
    int bid = blockIdx.x;
    int h = bid & 63, c = (bid >> 6) & 7, b = bid >> 9;
    int g = h >> 3;
    int base_tok = b * LSEQ + c * CHUNKL;
    float A_last = Acs[(size_t)bid * CHUNKL + 255];

    __shared__ float sX[8][64];
    __shared__ float sB[8][128];
    __shared__ float sdec[8];

    int n = threadIdx.x & 127;
    int dq = threadIdx.x >> 7;
    float acc[32];
    #pragma unroll
    for (int i = 0; i < 32; i++) acc[i] = 0.f;

    for (int t0 = 0; t0 < CHUNKL; t0 += 8) {
        for (int idx = threadIdx.x; idx < 8 * 64; idx += 256) {
            int r = idx >> 6, dd = idx & 63;
            sX[r][dd] = conv[(size_t)(base_tok + t0 + r) * CONV_DIMC + h * 64 + dd];
        }
        for (int idx = threadIdx.x; idx < 8 * 128; idx += 256) {
            int r = idx >> 7, nn = idx & 127;
            sB[r][nn] = conv[(size_t)(base_tok + t0 + r) * CONV_DIMC + D_INNER + g * 128 + nn];
        }
        if (threadIdx.x < 8)
            sdec[threadIdx.x] = expf(A_last - Acs[(size_t)bid * CHUNKL + t0 + threadIdx.x]);
        __syncthreads();
        #pragma unroll
        for (int r = 0; r < 8; r++) {
            float bv = sB[r][n] * sdec[r];
            #pragma unroll
            for (int i = 0; i < 32; i++) acc[i] += bv * sX[r][dq * 32 + i];
        }
        __syncthreads();
    }
    size_t base = (size_t)bid * (NSTATE * D_HEAD) + (size_t)n * D_HEAD + dq * 32;
    #pragma unroll
    for (int i = 0; i < 32; i++) states[base + i] = acc[i];
}

// ---------------- 7. inter-chunk scan ------------------------------------------
__global__ void k_scan(const float* __restrict__ states, const float* __restrict__ Acs,
                       float* __restrict__ hprev, float* __restrict__ hfinal) {
    int bh = blockIdx.x;
    int b = bh >> 6, h = bh & 63;
    float hv[32];
    #pragma unroll
    for (int k = 0; k < 32; k++) hv[k] = 0.f;
    for (int c = 0; c < NCHUNK; c++) {
        int bid = b * 512 + c * 64 + h;
        float cd = expf(Acs[(size_t)bid * CHUNKL + 255]);
        size_t base = (size_t)bid * (NSTATE * D_HEAD);
        #pragma unroll
        for (int k = 0; k < 32; k++) {
            int e = threadIdx.x + k * 256;
            hprev[base + e] = hv[k];
            hv[k] = hv[k] * cd + states[base + e];
        }
    }
    size_t obase = (size_t)bh * (NSTATE * D_HEAD);
    #pragma unroll
    for (int k = 0; k < 32; k++) hfinal[obase + threadIdx.x + k * 256] = hv[k];
}

// ---------------- 8. Y = Y_diag + Y_carry --------------------------------------
__global__ void k_y(const float* __restrict__ conv, const float* __restrict__ Acs,
                    const float* __restrict__ hprev, float* __restrict__ Y) {
    int bid = blockIdx.x;
    int tblk = bid & 3, h = (bid >> 2) & 63, c = (bid >> 8) & 7, b = bid >> 11;
    int g = h >> 3;
    int bch = b * 512 + c * 64 + h;
    int base_tok = b * LSEQ + c * CHUNKL;
    int t0 = tblk * 64;

    extern __shared__ float sm[];
    float* sAcs = sm;
    float* sC   = sAcs + 256;
    float* sB   = sC + 64 * 129;
    float* sX   = sB + 64 * 129;
    float* sP   = sX + 64 * 65;
    float* sH   = sP + 64 * 65;

    int tid = threadIdx.x;
    int i = tid >> 2;
    int q = tid & 3;

    if (tid < 256) sAcs[tid] = Acs[(size_t)bch * CHUNKL + tid];
    for (int idx = tid; idx < 64 * 128; idx += 256) {
        int r = idx >> 7, n = idx & 127;
        sC[r * 129 + n] = conv[(size_t)(base_tok + t0 + r) * CONV_DIMC + D_INNER + GN_ + g * 128 + n];
    }
    __syncthreads();

    float acc[16];
    #pragma unroll
    for (int d = 0; d < 16; d++) acc[d] = 0.f;

    for (int nt = 0; nt < 4; nt++) {
        for (int idx = tid; idx < 32 * 64; idx += 256) {
            int r = idx >> 6, dd = idx & 63;
            sH[r * 65 + dd] = hprev[(size_t)bch * (NSTATE * D_HEAD) + (size_t)(nt * 32 + r) * D_HEAD + dd];
        }
        __syncthreads();
        #pragma unroll
        for (int nl = 0; nl < 32; nl++) {
            float cv = sC[i * 129 + nt * 32 + nl];
            #pragma unroll
            for (int d = 0; d < 16; d++) acc[d] += cv * sH[nl * 65 + q * 16 + d];
        }
        __syncthreads();
    }
    {
        float eA = expf(sAcs[t0 + i]);
        #pragma unroll
        for (int d = 0; d < 16; d++) acc[d] *= eA;
    }

    for (int st = 0; st <= tblk; st++) {
        for (int idx = tid; idx < 64 * 128; idx += 256) {
            int r = idx >> 7, n = idx & 127;
            sB[r * 129 + n] = conv[(size_t)(base_tok + st * 64 + r) * CONV_DIMC + D_INNER + g * 128 + n];
        }
        for (int idx = tid; idx < 64 * 64; idx += 256) {
            int r = idx >> 6, dd = idx & 63;
            sX[r * 65 + dd] = conv[(size_t)(base_tok + st * 64 + r) * CONV_DIMC + h * 64 + dd];
        }
        __syncthreads();
        int tg = t0 + i;
        float at = sAcs[tg];
        #pragma unroll
        for (int jj = 0; jj < 16; jj++) {
            int j = q * 16 + jj;
            float p = 0.f;
            #pragma unroll
            for (int n = 0; n < 128; n++) p += sC[i * 129 + n] * sB[j * 129 + n];
            int sg = st * 64 + j;
            sP[i * 65 + j] = (sg <= tg) ? expf(at - sAcs[sg]) * p : 0.f;
        }
        __syncthreads();
        #pragma unroll
        for (int j = 0; j < 64; j++) {
            float pv = sP[i * 65 + j];
            #pragma unroll
            for (int d = 0; d < 16; d++) acc[d] += pv * sX[j * 65 + q * 16 + d];
        }
        __syncthreads();
    }

    int tok = base_tok + t0 + i;
    size_t obase = (size_t)tok * D_INNER + h * 64 + q * 16;
    #pragma unroll
    for (int d = 0; d < 16; d++) Y[obase + d] = acc[d];
}

// ---------------- 9. out-norm * silu(gate), in place on Y ----------------------
__global__ void k_ynorm(float* __restrict__ Y, const float* __restrict__ proj,
                        const float* __restrict__ w) {
    int tok = blockIdx.x;
    float* row = Y + (size_t)tok * D_INNER;
    __shared__ float red[256];
    float ss = 0.f;
    for (int i = threadIdx.x; i < D_INNER; i += 256) { float v = row[i]; ss += v * v; }
    red[threadIdx.x] = ss; __syncthreads();
    for (int o = 128; o > 0; o >>= 1) { if (threadIdx.x < o) red[threadIdx.x] += red[threadIdx.x + o]; __syncthreads(); }
    float rms = rsqrtf(red[0] / D_INNER + 1e-6f);
    const float* grow = proj + (size_t)tok * IN_PROJW + (D_INNER + HN + 2 * GN_);
    for (int i = threadIdx.x; i < D_INNER; i += 256) {
        float y = row[i] * rms * w[i];
        float gv = grow[i];
        row[i] = y * gv * sigmoidf_(gv);
    }
}

// ---------------- launch -------------------------------------------------------
extern "C" void kernel_launch(void* const* d_in, const int* in_sizes, int n_in,
                              void* d_out, int out_size) {
    const float* x       = (const float*)d_in[0];
    const float* norm_w  = (const float*)d_in[1];
    const float* inw     = (const float*)d_in[2];
    const float* cw      = (const float*)d_in[3];
    const float* cb      = (const float*)d_in[4];
    const float* cnw     = (const float*)d_in[5];
    const float* alog    = (const float*)d_in[6];
    const float* dtw     = (const float*)d_in[7];
    const float* dtb     = (const float*)d_in[8];
    const float* onw     = (const float*)d_in[9];
    const float* ow      = (const float*)d_in[10];
    float* out = (float*)d_out;

    float *xn, *proj, *conv, *Aval, *Acs, *states, *hprev, *Y;
    cudaGetSymbolAddress((void**)&xn,     g_xn);
    cudaGetSymbolAddress((void**)&proj,   g_proj);
    cudaGetSymbolAddress((void**)&conv,   g_conv);
    cudaGetSymbolAddress((void**)&Aval,   g_Aval);
    cudaGetSymbolAddress((void**)&Acs,    g_Acs);
    cudaGetSymbolAddress((void**)&states, g_states);
    cudaGetSymbolAddress((void**)&hprev,  g_hprev);
    cudaGetSymbolAddress((void**)&Y,      g_Y);

    cudaFuncSetAttribute(k_y, cudaFuncAttributeMaxDynamicSharedMemorySize, 120000);
    cudaFuncSetAttribute(k_gemm_tf32, cudaFuncAttributeMaxDynamicSharedMemorySize, 60000);
    size_t y_smem = (256 + 64 * 129 * 2 + 64 * 65 * 2 + 32 * 65) * sizeof(float);
    size_t g_smem = (2 * GT_ABUF + 2 * GT_BBUF) * sizeof(float);

    k_rms_x<<<NTOK, 256>>>(x, norm_w, xn);
    k_gemm_tf32<<<dim3(IN_PROJW / 64, NTOK / 128), 128, g_smem>>>(xn, inw, proj, nullptr, NTOK, IN_PROJW, D_MODEL);
    k_conv<<<NTOK, 256>>>(proj, cw, cb, cnw, conv);
    k_dt<<<NTOK / 4, 256>>>(proj, dtw, dtb, alog, Aval);
    k_cumsum<<<BB * NCHUNK * HN, CHUNKL>>>(Aval, Acs);
    k_states<<<BB * NCHUNK * HN, 256>>>(conv, Acs, states);
    k_scan<<<BB * HN, 256>>>(states, Acs, hprev, out + OUT_ELEMS);
    k_y<<<BB * NCHUNK * HN * 4, 256, y_smem>>>(conv, Acs, hprev, Y);
    k_ynorm<<<NTOK, 256>>>(Y, proj, onw);
    k_gemm_tf32<<<dim3(D_MODEL / 64, NTOK / 128), 128, g_smem>>>(Y, ow, out, x, NTOK, D_MODEL, D_INNER);
}

// round 12
// speedup vs baseline: 3.9594x; 1.6378x over previous
#include <cuda_runtime.h>
#include <math.h>
#include <stdint.h>

#define D_MODEL   2048
#define D_INNER   4096
#define HN        64
#define D_HEAD    64
#define NSTATE    128
#define GRP       8
#define CHUNKL    256
#define GN_       1024
#define CONV_DIMC 6144
#define IN_PROJW  10304
#define BB        2
#define LSEQ      2048
#define NTOK      4096      // BB*LSEQ
#define NCHUNK    8         // LSEQ/CHUNKL
#define OUT_ELEMS 8388608   // BB*LSEQ*D_MODEL

// ---------------- scratch (static device globals; allocation-free) -------------
__device__ float g_xn   [(size_t)NTOK * D_MODEL];
__device__ float g_proj [(size_t)NTOK * IN_PROJW];
__device__ float g_conv [(size_t)NTOK * CONV_DIMC];
__device__ float g_Aval [(size_t)NTOK * HN];
__device__ float g_Acs  [(size_t)BB * NCHUNK * HN * CHUNKL];
__device__ float g_states[(size_t)BB * NCHUNK * HN * NSTATE * D_HEAD];
__device__ float g_hprev [(size_t)BB * NCHUNK * HN * NSTATE * D_HEAD];
__device__ float g_Y    [(size_t)NTOK * D_INNER];

__device__ __forceinline__ float sigmoidf_(float v) { return 1.f / (1.f + expf(-v)); }
__device__ __forceinline__ float softplusf_(float v) { return v > 20.f ? v : log1pf(expf(v)); }
__device__ __forceinline__ float tf32r_(float x) {
    uint32_t u;
    asm("cvt.rna.tf32.f32 %0, %1;" : "=r"(u) : "f"(x));
    return __uint_as_float(u);
}
__device__ __forceinline__ void mma_tf32_(float* d, const uint32_t* a, const uint32_t* b) {
    asm volatile(
        "mma.sync.aligned.m16n8k8.row.col.f32.tf32.tf32.f32 "
        "{%0,%1,%2,%3}, {%4,%5,%6,%7}, {%8,%9}, {%0,%1,%2,%3};\n"
        : "+f"(d[0]), "+f"(d[1]), "+f"(d[2]), "+f"(d[3])
        : "r"(a[0]), "r"(a[1]), "r"(a[2]), "r"(a[3]), "r"(b[0]), "r"(b[1]));
}

// ---------------- 1. rmsnorm(x) -> xn ------------------------------------------
__global__ void k_rms_x(const float* __restrict__ x, const float* __restrict__ w,
                        float* __restrict__ out) {
    int tok = blockIdx.x;
    const float* row = x + (size_t)tok * D_MODEL;
    __shared__ float red[256];
    float ss = 0.f;
    for (int i = threadIdx.x; i < D_MODEL; i += 256) { float v = row[i]; ss += v * v; }
    red[threadIdx.x] = ss; __syncthreads();
    for (int o = 128; o > 0; o >>= 1) { if (threadIdx.x < o) red[threadIdx.x] += red[threadIdx.x + o]; __syncthreads(); }
    float rms = rsqrtf(red[0] / D_MODEL + 1e-6f);
    float* orow = out + (size_t)tok * D_MODEL;
    for (int i = threadIdx.x; i < D_MODEL; i += 256) orow[i] = row[i] * rms * w[i];
}

// ---------------- TF32 tensor-core GEMM: C[M,N] = A[M,K] @ B[N,K]^T (+resid) ---
#define GT_PAD 36
#define GT_ABUF (128 * GT_PAD)
#define GT_BBUF (64 * GT_PAD)
__global__ __launch_bounds__(128, 3)
void k_gemm_tf32(const float* __restrict__ A, const float* __restrict__ B,
                 float* __restrict__ C, const float* __restrict__ R,
                 int M, int N, int K) {
    extern __shared__ float sm[];
    float* sA = sm;                   // [2][128][36]
    float* sB = sm + 2 * GT_ABUF;     // [2][64][36]

    const int tid  = threadIdx.x;
    const int lane = tid & 31;
    const int w    = tid >> 5;
    const int wm   = w >> 1, wn = w & 1;
    const int g    = lane >> 2, tg = lane & 3;
    const int m0 = blockIdx.y * 128, n0 = blockIdx.x * 64;

    float4 pa[8], pb[4];
    #pragma unroll
    for (int p = 0; p < 8; p++) {
        int idx = tid + p * 128; int r = idx >> 3, c = idx & 7;
        pa[p] = *(const float4*)&A[(size_t)(m0 + r) * K + c * 4];
    }
    #pragma unroll
    for (int p = 0; p < 4; p++) {
        int idx = tid + p * 128; int r = idx >> 3, c = idx & 7;
        pb[p] = *(const float4*)&B[(size_t)(n0 + r) * K + c * 4];
    }

    float acc[4][4][4];
    #pragma unroll
    for (int mi = 0; mi < 4; mi++)
        #pragma unroll
        for (int ni = 0; ni < 4; ni++)
            #pragma unroll
            for (int e = 0; e < 4; e++) acc[mi][ni][e] = 0.f;

    const int nk = K >> 5;
    int buf = 0;

    #pragma unroll
    for (int p = 0; p < 8; p++) {
        int idx = tid + p * 128; int r = idx >> 3, c = idx & 7;
        float4 v = pa[p];
        v.x = tf32r_(v.x); v.y = tf32r_(v.y); v.z = tf32r_(v.z); v.w = tf32r_(v.w);
        *(float4*)&sA[r * GT_PAD + c * 4] = v;
    }
    #pragma unroll
    for (int p = 0; p < 4; p++) {
        int idx = tid + p * 128; int r = idx >> 3, c = idx & 7;
        float4 v = pb[p];
        v.x = tf32r_(v.x); v.y = tf32r_(v.y); v.z = tf32r_(v.z); v.w = tf32r_(v.w);
        *(float4*)&sB[r * GT_PAD + c * 4] = v;
    }
    __syncthreads();

    for (int kt = 0; kt < nk; kt++) {
        if (kt + 1 < nk) {
            int k0 = (kt + 1) * 32;
            #pragma unroll
            for (int p = 0; p < 8; p++) {
                int idx = tid + p * 128; int r = idx >> 3, c = idx & 7;
                pa[p] = *(const float4*)&A[(size_t)(m0 + r) * K + k0 + c * 4];
            }
            #pragma unroll
            for (int p = 0; p < 4; p++) {
                int idx = tid + p * 128; int r = idx >> 3, c = idx & 7;
                pb[p] = *(const float4*)&B[(size_t)(n0 + r) * K + k0 + c * 4];
            }
        }

        const float* cA = sA + buf * GT_ABUF + (wm * 64) * GT_PAD;
        const float* cB = sB + buf * GT_BBUF + (wn * 32) * GT_PAD;
        #pragma unroll
        for (int ks = 0; ks < 4; ks++) {
            const int kk = ks * 8;
            uint32_t af[4][4], bf[4][2];
            #pragma unroll
            for (int mi = 0; mi < 4; mi++) {
                af[mi][0] = __float_as_uint(cA[(mi * 16 + g) * GT_PAD + kk + tg]);
                af[mi][1] = __float_as_uint(cA[(mi * 16 + 8 + g) * GT_PAD + kk + tg]);
                af[mi][2] = __float_as_uint(cA[(mi * 16 + g) * GT_PAD + kk + tg + 4]);
                af[mi][3] = __float_as_uint(cA[(mi * 16 + 8 + g) * GT_PAD + kk + tg + 4]);
            }
            #pragma unroll
            for (int ni = 0; ni < 4; ni++) {
                bf[ni][0] = __float_as_uint(cB[(ni * 8 + g) * GT_PAD + kk + tg]);
                bf[ni][1] = __float_as_uint(cB[(ni * 8 + g) * GT_PAD + kk + tg + 4]);
            }
            #pragma unroll
            for (int mi = 0; mi < 4; mi++)
                #pragma unroll
                for (int ni = 0; ni < 4; ni++)
                    mma_tf32_(acc[mi][ni], af[mi], bf[ni]);
        }

        if (kt + 1 < nk) {
            int nb = buf ^ 1;
            #pragma unroll
            for (int p = 0; p < 8; p++) {
                int idx = tid + p * 128; int r = idx >> 3, c = idx & 7;
                float4 v = pa[p];
                v.x = tf32r_(v.x); v.y = tf32r_(v.y); v.z = tf32r_(v.z); v.w = tf32r_(v.w);
                *(float4*)&sA[nb * GT_ABUF + r * GT_PAD + c * 4] = v;
            }
            #pragma unroll
            for (int p = 0; p < 4; p++) {
                int idx = tid + p * 128; int r = idx >> 3, c = idx & 7;
                float4 v = pb[p];
                v.x = tf32r_(v.x); v.y = tf32r_(v.y); v.z = tf32r_(v.z); v.w = tf32r_(v.w);
                *(float4*)&sB[nb * GT_BBUF + r * GT_PAD + c * 4] = v;
            }
            __syncthreads();
            buf = nb;
        }
    }

    #pragma unroll
    for (int mi = 0; mi < 4; mi++) {
        #pragma unroll
        for (int ni = 0; ni < 4; ni++) {
            int row = m0 + wm * 64 + mi * 16 + g;
            int col = n0 + wn * 32 + ni * 8 + tg * 2;
            size_t o0 = (size_t)row * N + col;
            size_t o1 = (size_t)(row + 8) * N + col;
            float2 v0 = make_float2(acc[mi][ni][0], acc[mi][ni][1]);
            float2 v1 = make_float2(acc[mi][ni][2], acc[mi][ni][3]);
            if (R) {
                float2 r0 = *(const float2*)&R[o0];
                float2 r1 = *(const float2*)&R[o1];
                v0.x += r0.x; v0.y += r0.y; v1.x += r1.x; v1.y += r1.y;
            }
            *(float2*)&C[o0] = v0;
            *(float2*)&C[o1] = v1;
        }
    }
}

// ---------------- 3. conv4 + bias + rmsnorm + silu -> g_conv -------------------
__global__ void k_conv(const float* __restrict__ proj, const float* __restrict__ cw,
                       const float* __restrict__ cb, const float* __restrict__ nw,
                       float* __restrict__ out) {
    int tok = blockIdx.x;
    int l = tok & (LSEQ - 1);
    float v[24];
    float ss = 0.f;
    #pragma unroll
    for (int k = 0; k < 24; k++) {
        int c = threadIdx.x + k * 256;
        int pcol = (c < D_INNER) ? c : c + HN;
        float acc = cb[c];
        #pragma unroll
        for (int j = 0; j < 4; j++) {
            int lj = l + j - 3;
            if (lj >= 0)
                acc += cw[c * 4 + j] * proj[(size_t)(tok + j - 3) * IN_PROJW + pcol];
        }
        v[k] = acc;
        ss += acc * acc;
    }
    __shared__ float red[256];
    red[threadIdx.x] = ss; __syncthreads();
    for (int o = 128; o > 0; o >>= 1) { if (threadIdx.x < o) red[threadIdx.x] += red[threadIdx.x + o]; __syncthreads(); }
    float rms = rsqrtf(red[0] / CONV_DIMC + 1e-6f);
    #pragma unroll
    for (int k = 0; k < 24; k++) {
        int c = threadIdx.x + k * 256;
        float y = v[k] * rms * nw[c];
        out[(size_t)tok * CONV_DIMC + c] = y * sigmoidf_(y);
    }
}

// ---------------- 4. dt -> A (4 tokens per block) ------------------------------
__global__ void k_dt(const float* __restrict__ proj, const float* __restrict__ dtw,
                     const float* __restrict__ dtb, const float* __restrict__ alog,
                     float* __restrict__ Aout) {
    int sub = threadIdx.x >> 6;
    int h = threadIdx.x & 63;
    int tok = blockIdx.x * 4 + sub;
    __shared__ float sa[4][HN];
    sa[sub][h] = proj[(size_t)tok * IN_PROJW + D_INNER + h];
    __syncthreads();
    float acc = dtb[h];
    #pragma unroll
    for (int k = 0; k < HN; k++) acc += sa[sub][k] * dtw[h * HN + k];
    float dt = softplusf_(acc);
    Aout[(size_t)tok * HN + h] = -expf(alog[h]) * dt;
}

// ---------------- 5. cumsum of A per (b,c,h) -----------------------------------
__global__ void k_cumsum(const float* __restrict__ Aval, float* __restrict__ Acs) {
    int bid = blockIdx.x;
    int h = bid & 63, c = (bid >> 6) & 7, b = bid >> 9;
    int t = threadIdx.x;
    int tok = b * LSEQ + c * CHUNKL + t;
    __shared__ float s[CHUNKL];
    s[t] = Aval[(size_t)tok * HN + h];
    __syncthreads();
    for (int off = 1; off < CHUNKL; off <<= 1) {
        float add = (t >= off) ? s[t - off] : 0.f;
        __syncthreads();
        s[t] += add;
        __syncthreads();
    }
    Acs[(size_t)bid * CHUNKL + t] = s[t];
}

// ---------------- 6. per-chunk states[n,d] -------------------------------------
__global__ void k_states(const float* __restrict__ conv, const float* __restrict__ Acs,
                         float* __restrict__ states) {
    int bid = blockIdx.x;
    int h = bid & 63, c = (bid >> 6) & 7, b = bid >> 9;
    int g = h >> 3;
    int base_tok = b * LSEQ + c * CHUNKL;
    float A_last = Acs[(size_t)bid * CHUNKL + 255];

    __shared__ float sX[8][64];
    __shared__ float sB[8][128];
    __shared__ float sdec[8];

    int n = threadIdx.x & 127;
    int dq = threadIdx.x >> 7;
    float acc[32];
    #pragma unroll
    for (int i = 0; i < 32; i++) acc[i] = 0.f;

    for (int t0 = 0; t0 < CHUNKL; t0 += 8) {
        for (int idx = threadIdx.x; idx < 8 * 64; idx += 256) {
            int r = idx >> 6, dd = idx & 63;
            sX[r][dd] = conv[(size_t)(base_tok + t0 + r) * CONV_DIMC + h * 64 + dd];
        }
        for (int idx = threadIdx.x; idx < 8 * 128; idx += 256) {
            int r = idx >> 7, nn = idx & 127;
            sB[r][nn] = conv[(size_t)(base_tok + t0 + r) * CONV_DIMC + D_INNER + g * 128 + nn];
        }
        if (threadIdx.x < 8)
            sdec[threadIdx.x] = expf(A_last - Acs[(size_t)bid * CHUNKL + t0 + threadIdx.x]);
        __syncthreads();
        #pragma unroll
        for (int r = 0; r < 8; r++) {
            float bv = sB[r][n] * sdec[r];
            #pragma unroll
            for (int i = 0; i < 32; i++) acc[i] += bv * sX[r][dq * 32 + i];
        }
        __syncthreads();
    }
    size_t base = (size_t)bid * (NSTATE * D_HEAD) + (size_t)n * D_HEAD + dq * 32;
    #pragma unroll
    for (int i = 0; i < 32; i++) states[base + i] = acc[i];
}

// ---------------- 7. inter-chunk scan ------------------------------------------
__global__ void k_scan(const float* __restrict__ states, const float* __restrict__ Acs,
                       float* __restrict__ hprev, float* __restrict__ hfinal) {
    int bh = blockIdx.x;
    int b = bh >> 6, h = bh & 63;
    float hv[32];
    #pragma unroll
    for (int k = 0; k < 32; k++) hv[k] = 0.f;
    for (int c = 0; c < NCHUNK; c++) {
        int bid = b * 512 + c * 64 + h;
        float cd = expf(Acs[(size_t)bid * CHUNKL + 255]);
        size_t base = (size_t)bid * (NSTATE * D_HEAD);
        #pragma unroll
        for (int k = 0; k < 32; k++) {
            int e = threadIdx.x + k * 256;
            hprev[base + e] = hv[k];
            hv[k] = hv[k] * cd + states[base + e];
        }
    }
    size_t obase = (size_t)bh * (NSTATE * D_HEAD);
    #pragma unroll
    for (int k = 0; k < 32; k++) hfinal[obase + threadIdx.x + k * 256] = hv[k];
}

// ---------------- 8. Y via TF32 MMA --------------------------------------------
// grid: b*2048 + c*256 + h*4 + tblk (4096 blocks), 128 threads = 4 warps (2x2).
// Y[64t x 64d] = exp(Acs)*(C @ hprev) + sum_st maskexp(C @ B^T) @ X
// smem: sAcs 256 | sC 64x132 | sBH 64x133 (hprev^T, then B) | sXT 64x69 | sP 64x68
#define YP_C  132
#define YP_BH 133
#define YP_XT 69
#define YP_P  68
__global__ __launch_bounds__(128, 2)
void k_y_mma(const float* __restrict__ conv, const float* __restrict__ Acs,
             const float* __restrict__ hprev, float* __restrict__ Y) {
    int bid = blockIdx.x;
    int tblk = bid & 3, h = (bid >> 2) & 63, c = (bid >> 8) & 7, b = bid >> 11;
    int g8 = h >> 3;
    int bch = b * 512 + c * 64 + h;
    int base_tok = b * LSEQ + c * CHUNKL;
    int t0 = tblk * 64;

    extern __shared__ float sm[];
    float* sAcs = sm;                       // 256
    float* sC   = sAcs + 256;               // 64*132
    float* sBH  = sC + 64 * YP_C;           // 64*133
    float* sXT  = sBH + 64 * YP_BH;         // 64*69
    float* sP   = sXT + 64 * YP_XT;         // 64*68

    const int tid  = threadIdx.x;
    const int lane = tid & 31;
    const int w    = tid >> 5;
    const int wm   = w >> 1, wn = w & 1;
    const int g    = lane >> 2, tg = lane & 3;

    for (int i = tid; i < 256; i += 128) sAcs[i] = Acs[(size_t)bch * CHUNKL + i];
    // C tile [t][n], tf32
    for (int idx = tid; idx < 64 * 128; idx += 128) {
        int r = idx >> 7, n = idx & 127;
        sC[r * YP_C + n] = tf32r_(conv[(size_t)(base_tok + t0 + r) * CONV_DIMC + D_INNER + GN_ + g8 * 128 + n]);
    }
    // hprev^T [d][n], tf32 (coalesced read: n-major, d inner)
    {
        size_t hbase = (size_t)bch * (NSTATE * D_HEAD);
        for (int idx = tid; idx < 128 * 64; idx += 128) {
            int n = idx >> 6, d = idx & 63;
            sBH[d * YP_BH + n] = tf32r_(hprev[hbase + (size_t)n * D_HEAD + d]);
        }
    }
    __syncthreads();

    float yacc[2][4][4];
    #pragma unroll
    for (int mi = 0; mi < 2; mi++)
        #pragma unroll
        for (int ni = 0; ni < 4; ni++)
            #pragma unroll
            for (int e = 0; e < 4; e++) yacc[mi][ni][e] = 0.f;

    // ---- carry: Y = C @ hprev  (K = 128) ----
    #pragma unroll
    for (int kk = 0; kk < 128; kk += 8) {
        uint32_t af[2][4], bf[4][2];
        #pragma unroll
        for (int mi = 0; mi < 2; mi++) {
            int r = wm * 32 + mi * 16;
            af[mi][0] = __float_as_uint(sC[(r + g) * YP_C + kk + tg]);
            af[mi][1] = __float_as_uint(sC[(r + 8 + g) * YP_C + kk + tg]);
            af[mi][2] = __float_as_uint(sC[(r + g) * YP_C + kk + tg + 4]);
            af[mi][3] = __float_as_uint(sC[(r + 8 + g) * YP_C + kk + tg + 4]);
        }
        #pragma unroll
        for (int ni = 0; ni < 4; ni++) {
            int d = wn * 32 + ni * 8 + g;
            bf[ni][0] = __float_as_uint(sBH[d * YP_BH + kk + tg]);
            bf[ni][1] = __float_as_uint(sBH[d * YP_BH + kk + tg + 4]);
        }
        #pragma unroll
        for (int mi = 0; mi < 2; mi++)
            #pragma unroll
            for (int ni = 0; ni < 4; ni++)
                mma_tf32_(yacc[mi][ni], af[mi], bf[ni]);
    }
    // scale by exp(Acs[t])
    #pragma unroll
    for (int mi = 0; mi < 2; mi++) {
        int r = t0 + wm * 32 + mi * 16 + g;
        float e0 = expf(sAcs[r]), e1 = expf(sAcs[r + 8]);
        #pragma unroll
        for (int ni = 0; ni < 4; ni++) {
            yacc[mi][ni][0] *= e0; yacc[mi][ni][1] *= e0;
            yacc[mi][ni][2] *= e1; yacc[mi][ni][3] *= e1;
        }
    }
    __syncthreads();   // done reading hprev^T before sBH is reused for B

    // ---- diag: over s-tiles ----
    for (int st = 0; st <= tblk; st++) {
        for (int idx = tid; idx < 64 * 128; idx += 128) {
            int r = idx >> 7, n = idx & 127;
            sBH[r * YP_BH + n] = tf32r_(conv[(size_t)(base_tok + st * 64 + r) * CONV_DIMC + D_INNER + g8 * 128 + n]);
        }
        for (int idx = tid; idx < 64 * 64; idx += 128) {
            int s = idx >> 6, d = idx & 63;
            sXT[d * YP_XT + s] = tf32r_(conv[(size_t)(base_tok + st * 64 + s) * CONV_DIMC + h * 64 + d]);
        }
        __syncthreads();

        // P = C @ B^T  (K = 128)
        float pacc[2][4][4];
        #pragma unroll
        for (int mi = 0; mi < 2; mi++)
            #pragma unroll
            for (int ni = 0; ni < 4; ni++)
                #pragma unroll
                for (int e = 0; e < 4; e++) pacc[mi][ni][e] = 0.f;
        #pragma unroll
        for (int kk = 0; kk < 128; kk += 8) {
            uint32_t af[2][4], bf[4][2];
            #pragma unroll
            for (int mi = 0; mi < 2; mi++) {
                int r = wm * 32 + mi * 16;
                af[mi][0] = __float_as_uint(sC[(r + g) * YP_C + kk + tg]);
                af[mi][1] = __float_as_uint(sC[(r + 8 + g) * YP_C + kk + tg]);
                af[mi][2] = __float_as_uint(sC[(r + g) * YP_C + kk + tg + 4]);
                af[mi][3] = __float_as_uint(sC[(r + 8 + g) * YP_C + kk + tg + 4]);
            }
            #pragma unroll
            for (int ni = 0; ni < 4; ni++) {
                int s = wn * 32 + ni * 8 + g;
                bf[ni][0] = __float_as_uint(sBH[s * YP_BH + kk + tg]);
                bf[ni][1] = __float_as_uint(sBH[s * YP_BH + kk + tg + 4]);
            }
            #pragma unroll
            for (int mi = 0; mi < 2; mi++)
                #pragma unroll
                for (int ni = 0; ni < 4; ni++)
                    mma_tf32_(pacc[mi][ni], af[mi], bf[ni]);
        }
        // mask + exp, write P to smem (tf32)
        #pragma unroll
        for (int mi = 0; mi < 2; mi++) {
            int r0l = wm * 32 + mi * 16 + g;     // local t row (0..63)
            int r1l = r0l + 8;
            int tg0 = t0 + r0l, tg1 = t0 + r1l;  // global-in-chunk t
            float at0 = sAcs[tg0], at1 = sAcs[tg1];
            #pragma unroll
            for (int ni = 0; ni < 4; ni++) {
                int sl = wn * 32 + ni * 8 + tg * 2;   // local s col
                int sg0 = st * 64 + sl, sg1 = sg0 + 1;
                float p00 = (sg0 <= tg0) ? expf(at0 - sAcs[sg0]) * pacc[mi][ni][0] : 0.f;
                float p01 = (sg1 <= tg0) ? expf(at0 - sAcs[sg1]) * pacc[mi][ni][1] : 0.f;
                float p10 = (sg0 <= tg1) ? expf(at1 - sAcs[sg0]) * pacc[mi][ni][2] : 0.f;
                float p11 = (sg1 <= tg1) ? expf(at1 - sAcs[sg1]) * pacc[mi][ni][3] : 0.f;
                *(float2*)&sP[r0l * YP_P + sl] = make_float2(tf32r_(p00), tf32r_(p01));
                *(float2*)&sP[r1l * YP_P + sl] = make_float2(tf32r_(p10), tf32r_(p11));
            }
        }
        __syncthreads();

        // Y += P @ X  (K = 64)
        #pragma unroll
        for (int kk = 0; kk < 64; kk += 8) {
            uint32_t af[2][4], bf[4][2];
            #pragma unroll
            for (int mi = 0; mi < 2; mi++) {
                int r = wm * 32 + mi * 16;
                af[mi][0] = __float_as_uint(sP[(r + g) * YP_P + kk + tg]);
                af[mi][1] = __float_as_uint(sP[(r + 8 + g) * YP_P + kk + tg]);
                af[mi][2] = __float_as_uint(sP[(r + g) * YP_P + kk + tg + 4]);
                af[mi][3] = __float_as_uint(sP[(r + 8 + g) * YP_P + kk + tg + 4]);
            }
            #pragma unroll
            for (int ni = 0; ni < 4; ni++) {
                int d = wn * 32 + ni * 8 + g;
                bf[ni][0] = __float_as_uint(sXT[d * YP_XT + kk + tg]);
                bf[ni][1] = __float_as_uint(sXT[d * YP_XT + kk + tg + 4]);
            }
            #pragma unroll
            for (int mi = 0; mi < 2; mi++)
                #pragma unroll
                for (int ni = 0; ni < 4; ni++)
                    mma_tf32_(yacc[mi][ni], af[mi], bf[ni]);
        }
        __syncthreads();   // before next st overwrites sBH/sXT
    }

    // store Y
    #pragma unroll
    for (int mi = 0; mi < 2; mi++) {
        int r = wm * 32 + mi * 16 + g;
        int tok0 = base_tok + t0 + r;
        #pragma unroll
        for (int ni = 0; ni < 4; ni++) {
            int col = h * 64 + wn * 32 + ni * 8 + tg * 2;
            *(float2*)&Y[(size_t)tok0 * D_INNER + col]       = make_float2(yacc[mi][ni][0], yacc[mi][ni][1]);
            *(float2*)&Y[(size_t)(tok0 + 8) * D_INNER + col] = make_float2(yacc[mi][ni][2], yacc[mi][ni][3]);
        }
    }
}

// ---------------- 9. out-norm * silu(gate), in place on Y ----------------------
__global__ void k_ynorm(float* __restrict__ Y, const float* __restrict__ proj,
                        const float* __restrict__ w) {
    int tok = blockIdx.x;
    float* row = Y + (size_t)tok * D_INNER;
    __shared__ float red[256];
    float ss = 0.f;
    for (int i = threadIdx.x; i < D_INNER; i += 256) { float v = row[i]; ss += v * v; }
    red[threadIdx.x] = ss; __syncthreads();
    for (int o = 128; o > 0; o >>= 1) { if (threadIdx.x < o) red[threadIdx.x] += red[threadIdx.x + o]; __syncthreads(); }
    float rms = rsqrtf(red[0] / D_INNER + 1e-6f);
    const float* grow = proj + (size_t)tok * IN_PROJW + (D_INNER + HN + 2 * GN_);
    for (int i = threadIdx.x; i < D_INNER; i += 256) {
        float y = row[i] * rms * w[i];
        float gv = grow[i];
        row[i] = y * gv * sigmoidf_(gv);
    }
}

// ---------------- launch -------------------------------------------------------
extern "C" void kernel_launch(void* const* d_in, const int* in_sizes, int n_in,
                              void* d_out, int out_size) {
    const float* x       = (const float*)d_in[0];
    const float* norm_w  = (const float*)d_in[1];
    const float* inw     = (const float*)d_in[2];
    const float* cw      = (const float*)d_in[3];
    const float* cb      = (const float*)d_in[4];
    const float* cnw     = (const float*)d_in[5];
    const float* alog    = (const float*)d_in[6];
    const float* dtw     = (const float*)d_in[7];
    const float* dtb     = (const float*)d_in[8];
    const float* onw     = (const float*)d_in[9];
    const float* ow      = (const float*)d_in[10];
    float* out = (float*)d_out;

    float *xn, *proj, *conv, *Aval, *Acs, *states, *hprev, *Y;
    cudaGetSymbolAddress((void**)&xn,     g_xn);
    cudaGetSymbolAddress((void**)&proj,   g_proj);
    cudaGetSymbolAddress((void**)&conv,   g_conv);
    cudaGetSymbolAddress((void**)&Aval,   g_Aval);
    cudaGetSymbolAddress((void**)&Acs,    g_Acs);
    cudaGetSymbolAddress((void**)&states, g_states);
    cudaGetSymbolAddress((void**)&hprev,  g_hprev);
    cudaGetSymbolAddress((void**)&Y,      g_Y);

    cudaFuncSetAttribute(k_y_mma, cudaFuncAttributeMaxDynamicSharedMemorySize, 110000);
    cudaFuncSetAttribute(k_gemm_tf32, cudaFuncAttributeMaxDynamicSharedMemorySize, 60000);
    size_t y_smem = (256 + 64 * YP_C + 64 * YP_BH + 64 * YP_XT + 64 * YP_P) * sizeof(float);
    size_t g_smem = (2 * GT_ABUF + 2 * GT_BBUF) * sizeof(float);

    k_rms_x<<<NTOK, 256>>>(x, norm_w, xn);
    k_gemm_tf32<<<dim3(IN_PROJW / 64, NTOK / 128), 128, g_smem>>>(xn, inw, proj, nullptr, NTOK, IN_PROJW, D_MODEL);
    k_conv<<<NTOK, 256>>>(proj, cw, cb, cnw, conv);
    k_dt<<<NTOK / 4, 256>>>(proj, dtw, dtb, alog, Aval);
    k_cumsum<<<BB * NCHUNK * HN, CHUNKL>>>(Aval, Acs);
    k_states<<<BB * NCHUNK * HN, 256>>>(conv, Acs, states);
    k_scan<<<BB * HN, 256>>>(states, Acs, hprev, out + OUT_ELEMS);
    k_y_mma<<<BB * NCHUNK * HN * 4, 128, y_smem>>>(conv, Acs, hprev, Y);
    k_ynorm<<<NTOK, 256>>>(Y, proj, onw);
    k_gemm_tf32<<<dim3(D_MODEL / 64, NTOK / 128), 128, g_smem>>>(Y, ow, out, x, NTOK, D_MODEL, D_INNER);
}